// round 15
// baseline (speedup 1.0000x reference)
#include <cuda_runtime.h>
#include <cstdint>

typedef unsigned long long ull;

#define NN_MAX 100000
#define LDIM 64
#define HD 32
#define EDIM 4
#define NCOL 36   // 32 (W1) + 4 (W_direct) fused columns

// ---- constant-memory weight block (published via async memcpy from g_stage)
struct WConst {
    float wd[LDIM * NCOL];   // Wdiff = W[64:] - W[:64], fused [W1|Wd]
    float w2[HD * HD];
    float w3[HD * EDIM];
    float b1[HD];
    float b2[HD];
    float bo[EDIM];          // b3 + bd
};
__constant__ __align__(16) WConst c_w;
__device__   __align__(16) WConst g_stage;

// smem: flag + per-warp tiles only (weights live in constant space)
#define FLAG_OFF  0
#define TILE_OFF  4                         // 16 B aligned
#define M_CH      20                        // chunk row stride (5 f4, odd -> conflict-free)
#define EPW       32                        // edges per warp (EPT=1)
#define PER_WARP  1152                      // m-chunk (32*20=640) / u (32*36=1152) aliased
#define NWARPS    4
#define SMEM_FLOATS (TILE_OFF + NWARPS * PER_WARP)  // 4612
#define SMEM_BYTES  (SMEM_FLOATS * 4)               // 18448 -> smem allows 6+ blocks

// Scratch: u[node][j] = sum_{k<64} x[node][k] * [W1 | Wd][k][j]
__device__ __align__(16) float g_u[NN_MAX * NCOL];

__device__ __forceinline__ ull pack2(float a) {
    ull r; asm("mov.b64 %0, {%1, %1};" : "=l"(r) : "f"(a)); return r;
}
__device__ __forceinline__ ull fma2(ull a, ull b, ull c) {
    ull d; asm("fma.rn.f32x2 %0, %1, %2, %3;" : "=l"(d) : "l"(a), "l"(b), "l"(c)); return d;
}
__device__ __forceinline__ ull add2(ull a, ull b) {
    ull d; asm("add.rn.f32x2 %0, %1, %2;" : "=l"(d) : "l"(a), "l"(b)); return d;
}
__device__ __forceinline__ void unpack2(ull v, float& lo, float& hi) {
    asm("mov.b64 {%0, %1}, %2;" : "=f"(lo), "=f"(hi) : "l"(v));
}

// ---------------------------------------------------------------------------
// Kernel 0: derive Wdiff / combined biases into the staging struct.
// ---------------------------------------------------------------------------
__global__ void __launch_bounds__(256) prep_weights(
    const float* __restrict__ W1, const float* __restrict__ b1,
    const float* __restrict__ Wd, const float* __restrict__ bd,
    const float* __restrict__ W2, const float* __restrict__ b2,
    const float* __restrict__ W3, const float* __restrict__ b3)
{
    int tid = blockIdx.x * 256 + threadIdx.x;
    const int NT = 4 * 256;
    for (int i = tid; i < LDIM * NCOL; i += NT) {
        int k = i / NCOL, j = i - k * NCOL;
        float hi, lo;
        if (j < HD) { hi = W1[(LDIM + k) * HD + j];        lo = W1[k * HD + j]; }
        else        { hi = Wd[(LDIM + k) * EDIM + (j-HD)]; lo = Wd[k * EDIM + (j-HD)]; }
        g_stage.wd[i] = hi - lo;
    }
    for (int i = tid; i < HD * HD; i += NT)   g_stage.w2[i] = W2[i];
    for (int i = tid; i < HD * EDIM; i += NT) g_stage.w3[i] = W3[i];
    if (tid < HD)  { g_stage.b1[tid] = b1[tid]; g_stage.b2[tid] = b2[tid]; }
    if (tid < EDIM) g_stage.bo[tid] = b3[tid] + bd[tid];
}

// ---------------------------------------------------------------------------
// Kernel 1: per-node precompute u = x[:, :] @ [W1[:64] | Wd[:64]]
// ---------------------------------------------------------------------------
__global__ void __launch_bounds__(256) precompute_u(
    const float* __restrict__ x,
    const float* __restrict__ W1,
    const float* __restrict__ Wd,
    int n_nodes)
{
    __shared__ __align__(16) float sW[LDIM][NCOL];
    int tid = threadIdx.x;
    for (int i = tid; i < LDIM * NCOL; i += 256) {
        int k = i / NCOL, j = i - k * NCOL;
        sW[k][j] = (j < HD) ? W1[k * HD + j] : Wd[k * EDIM + (j - HD)];
    }
    __syncthreads();

    int node = blockIdx.x * 256 + tid;
    if (node >= n_nodes) return;

    float acc[NCOL];
    #pragma unroll
    for (int j = 0; j < NCOL; j++) acc[j] = 0.f;

    const float4* xr = (const float4*)(x + (size_t)node * LDIM);
    #pragma unroll 4
    for (int k4 = 0; k4 < LDIM / 4; k4++) {
        float4 v = __ldg(xr + k4);
        #pragma unroll
        for (int j = 0; j < NCOL; j++) {
            acc[j] = fmaf(v.x, sW[4 * k4 + 0][j], acc[j]);
            acc[j] = fmaf(v.y, sW[4 * k4 + 1][j], acc[j]);
            acc[j] = fmaf(v.z, sW[4 * k4 + 2][j], acc[j]);
            acc[j] = fmaf(v.w, sW[4 * k4 + 3][j], acc[j]);
        }
    }
    float4* ur = (float4*)(g_u + (size_t)node * NCOL);
    #pragma unroll
    for (int j4 = 0; j4 < NCOL / 4; j4++) {
        float4 r;
        r.x = acc[4 * j4 + 0]; r.y = acc[4 * j4 + 1];
        r.z = acc[4 * j4 + 2]; r.w = acc[4 * j4 + 3];
        ur[j4] = r;
    }
}

// ---------------------------------------------------------------------------
// Kernel 2: warp-cooperative edge MLP, 1 edge/thread, k-chunked m-tile,
// m/u tiles aliased, weights in __constant__ (uniform-port LDCU).
// Small regs + small smem -> 6 blocks/SM (24 warps).
// ---------------------------------------------------------------------------
__global__ void __launch_bounds__(128, 6) edge_kernel(
    const float* __restrict__ x,
    const void* __restrict__ ei,
    float* __restrict__ out, int n_edges, int n_nodes)
{
    extern __shared__ __align__(16) float dsm[];

    int tid = threadIdx.x;
    if (tid == 0) {
        // dtype probe: int32 data read as int64 pairs -> values outside [0,n)
        const long long* p = (const long long*)ei;
        int ok = 1;
        for (int i = 0; i < 64; i++) {
            long long v = p[i];
            if (v < 0 || v >= n_nodes) { ok = 0; break; }
        }
        ((int*)dsm)[FLAG_OFF] = ok;
    }
    __syncthreads();
    int s_is64 = ((const int*)dsm)[FLAG_OFF];

    int warp = tid >> 5, lane = tid & 31;
    int tile_base = (blockIdx.x * NWARPS + warp) * EPW;
    if (tile_base >= n_edges) return;

    int e  = tile_base + lane;
    int ec = (e < n_edges) ? e : (n_edges - 1);

    // ---- index load: dtype-flexible, clamped (never IMA) ----
    unsigned s, t;
    if (s_is64) {
        s = (unsigned)((const long long*)ei)[ec];
        t = (unsigned)((const long long*)ei)[(size_t)n_edges + ec];
    } else {
        s = (unsigned)((const int*)ei)[ec];
        t = (unsigned)((const int*)ei)[(size_t)n_edges + ec];
    }
    unsigned nm1 = (unsigned)(n_nodes - 1);
    s = (s < nm1) ? s : nm1;
    t = (t < nm1) ? t : nm1;

    float* sm_m = dsm + TILE_OFF + warp * PER_WARP;   // [32][M_CH] chunk tile
    float* sm_u = sm_m;                               // [32][NCOL], aliased

    const unsigned FULL = 0xffffffffu;
    int half  = lane >> 4;        // 0 = s-row, 1 = t-row
    int li    = lane & 15;
    int esub4 = li >> 2;          // edge-within-pass (0..3)
    int f     = lane & 3;         // float4-within-chunk (0..3)

    // ================= GEMM1 in 4 k-chunks of 16 =================
    ull acc[NCOL / 2];
    #pragma unroll
    for (int i = 0; i < NCOL / 2; i++) acc[i] = 0ULL;

    #pragma unroll 1
    for (int c = 0; c < 4; c++) {
        __syncwarp();
        // gather chunk c: 8 passes x 4 edges; lanes 0-15 s-rows, 16-31 t-rows
        #pragma unroll 4
        for (int pass = 0; pass < 8; pass++) {
            int ee = pass * 4 + esub4;
            unsigned sr = __shfl_sync(FULL, s, ee);
            unsigned tr = __shfl_sync(FULL, t, ee);
            unsigned row = half ? tr : sr;
            const float4* px = (const float4*)(x + (size_t)row * LDIM + c * 16);
            float4 v = __ldg(px + f);
            float4 m;
            m.x = fmaxf(v.x, __shfl_xor_sync(FULL, v.x, 16));
            m.y = fmaxf(v.y, __shfl_xor_sync(FULL, v.y, 16));
            m.z = fmaxf(v.z, __shfl_xor_sync(FULL, v.z, 16));
            m.w = fmaxf(v.w, __shfl_xor_sync(FULL, v.w, 16));
            if (lane < 16) *(float4*)(sm_m + ee * M_CH + f * 4) = m;
        }
        __syncwarp();
        // partial GEMM over this chunk's 16 k-values
        #pragma unroll
        for (int k4 = 0; k4 < 4; k4++) {
            float4 mv = *(const float4*)(sm_m + lane * M_CH + k4 * 4);
            float a4[4] = {mv.x, mv.y, mv.z, mv.w};
            #pragma unroll
            for (int kk = 0; kk < 4; kk++) {
                ull ma = pack2(a4[kk]);
                const ulonglong2* wr = (const ulonglong2*)
                    (c_w.wd + (c * 16 + k4 * 4 + kk) * NCOL);
                #pragma unroll
                for (int j4 = 0; j4 < NCOL / 4; j4++) {
                    ulonglong2 w = wr[j4];
                    acc[2 * j4 + 0] = fma2(ma, w.x, acc[2 * j4 + 0]);
                    acc[2 * j4 + 1] = fma2(ma, w.y, acc[2 * j4 + 1]);
                }
            }
        }
    }

    // ---- u gather into the (now dead) m-tile buffer ----
    __syncwarp();
    #pragma unroll 4
    for (int ee = 0; ee < EPW; ee++) {
        unsigned sr = __shfl_sync(FULL, s, ee);
        unsigned tr = __shfl_sync(FULL, t, ee);
        unsigned row = half ? tr : sr;
        const float4* pu = (const float4*)(g_u + (size_t)row * NCOL);
        int uli = (li < 9) ? li : 8;
        float4 uv = __ldg(pu + uli);
        float4 us;
        us.x = uv.x + __shfl_xor_sync(FULL, uv.x, 16);
        us.y = uv.y + __shfl_xor_sync(FULL, uv.y, 16);
        us.z = uv.z + __shfl_xor_sync(FULL, uv.z, 16);
        us.w = uv.w + __shfl_xor_sync(FULL, uv.w, 16);
        if (lane < 9) *(float4*)(sm_u + ee * NCOL + li * 4) = us;
    }
    __syncwarp();

    // add presummed u_s + u_t
    const ulonglong2* uu = (const ulonglong2*)(sm_u + lane * NCOL);
    #pragma unroll
    for (int j4 = 0; j4 < NCOL / 4; j4++) {
        ulonglong2 w = uu[j4];
        acc[2 * j4 + 0] = add2(acc[2 * j4 + 0], w.x);
        acc[2 * j4 + 1] = add2(acc[2 * j4 + 1], w.y);
    }

    // ================= tail: bias+relu -> GEMM2 -> GEMM3 =================
    float h[HD], cd[EDIM];
    #pragma unroll
    for (int i = 0; i < HD / 2; i++) {
        float lo, hi; unpack2(acc[i], lo, hi);
        h[2 * i + 0] = fmaxf(lo + c_w.b1[2 * i + 0], 0.f);
        h[2 * i + 1] = fmaxf(hi + c_w.b1[2 * i + 1], 0.f);
    }
    unpack2(acc[16], cd[0], cd[1]);
    unpack2(acc[17], cd[2], cd[3]);

    // GEMM2: h @ W2
    ull acc2[HD / 2];
    #pragma unroll
    for (int i = 0; i < HD / 2; i++) acc2[i] = 0ULL;
    #pragma unroll 8
    for (int k = 0; k < HD; k++) {
        ull hk = pack2(h[k]);
        const ulonglong2* wr = (const ulonglong2*)(c_w.w2 + k * HD);
        #pragma unroll
        for (int j4 = 0; j4 < HD / 4; j4++) {
            ulonglong2 w = wr[j4];
            acc2[2 * j4 + 0] = fma2(hk, w.x, acc2[2 * j4 + 0]);
            acc2[2 * j4 + 1] = fma2(hk, w.y, acc2[2 * j4 + 1]);
        }
    }
    // residual + relu, h <- h2
    #pragma unroll
    for (int i = 0; i < HD / 2; i++) {
        float lo, hi; unpack2(acc2[i], lo, hi);
        h[2 * i + 0] = fmaxf(lo + c_w.b2[2 * i + 0] + h[2 * i + 0], 0.f);
        h[2 * i + 1] = fmaxf(hi + c_w.b2[2 * i + 1] + h[2 * i + 1], 0.f);
    }

    // GEMM3: h2 @ W3
    ull o01 = 0ULL, o23 = 0ULL;
    #pragma unroll 8
    for (int k = 0; k < HD; k++) {
        ull hk = pack2(h[k]);
        ulonglong2 w = *(const ulonglong2*)(c_w.w3 + k * EDIM);
        o01 = fma2(hk, w.x, o01);
        o23 = fma2(hk, w.y, o23);
    }

    if (e < n_edges) {
        float a, b;
        float4 r;
        unpack2(o01, a, b);
        r.x = a + cd[0] + c_w.bo[0];
        r.y = b + cd[1] + c_w.bo[1];
        unpack2(o23, a, b);
        r.z = a + cd[2] + c_w.bo[2];
        r.w = b + cd[3] + c_w.bo[3];
        ((float4*)out)[e] = r;
    }
}

// ---------------------------------------------------------------------------
extern "C" void kernel_launch(void* const* d_in, const int* in_sizes, int n_in,
                              void* d_out, int out_size) {
    const float* x  = (const float*)d_in[0];
    const void*  ei = d_in[1];
    const float* Wd = (const float*)d_in[2];
    const float* bd = (const float*)d_in[3];
    const float* W1 = (const float*)d_in[4];
    const float* b1 = (const float*)d_in[5];
    const float* W2 = (const float*)d_in[6];
    const float* b2 = (const float*)d_in[7];
    const float* W3 = (const float*)d_in[8];
    const float* b3 = (const float*)d_in[9];
    float* out = (float*)d_out;

    int n_nodes = in_sizes[0] / LDIM;
    if (n_nodes > NN_MAX) n_nodes = NN_MAX;
    int n_edges = in_sizes[1] / 2;

    static int attr_done = 0;
    static void* stage_ptr = nullptr;
    if (!attr_done) {
        cudaFuncSetAttribute(edge_kernel,
                             cudaFuncAttributeMaxDynamicSharedMemorySize,
                             SMEM_BYTES);
        cudaGetSymbolAddress(&stage_ptr, g_stage);
        attr_done = 1;
    }

    // 0) derive weights into staging, publish to constant space (D2D memcpy
    //    node — graph-capturable, no allocation)
    prep_weights<<<4, 256>>>(W1, b1, Wd, bd, W2, b2, W3, b3);
    cudaMemcpyToSymbolAsync(c_w, stage_ptr, sizeof(WConst), 0,
                            cudaMemcpyDeviceToDevice, 0);

    // 1) per-node precompute
    precompute_u<<<(n_nodes + 255) / 256, 256>>>(x, W1, Wd, n_nodes);

    // 2) per-edge MLP
    int edges_per_block = NWARPS * EPW;   // 128
    int blocks = (n_edges + edges_per_block - 1) / edges_per_block;
    edge_kernel<<<blocks, 128, SMEM_BYTES>>>(x, ei, out, n_edges, n_nodes);
}